// round 4
// baseline (speedup 1.0000x reference)
#include <cuda_runtime.h>
#include <math.h>

// Problem constants
#define NB   16
#define CIN  512
#define COUT 512
#define HH   64
#define WW   64
#define HW   (HH*WW)           // 4096
#define STY  512
#define KT   9                 // 3x3 taps

typedef unsigned long long u64;

// Scratch (device globals — allocation-free rule)
__device__ float g_s[NB*CIN];            // modulation scales s[n][ci]
__device__ float g_wsq[COUT*CIN];        // sum_k weight^2 per (co,ci)
__device__ float g_demod[NB*COUT];       // demod[n][co]
__device__ float g_wt[CIN*KT*COUT];      // transposed weights [ci][tap][co]

// packed f32x2 helpers
__device__ __forceinline__ u64 ffma2(u64 a, u64 b, u64 c) {
    u64 d;
    asm("fma.rn.f32x2 %0, %1, %2, %3;" : "=l"(d) : "l"(a), "l"(b), "l"(c));
    return d;
}
__device__ __forceinline__ u64 pk2(float x) {
    u64 d;
    asm("mov.b64 %0, {%1, %1};" : "=l"(d) : "f"(x));
    return d;
}
__device__ __forceinline__ void unpk2(u64 a, float& lo, float& hi) {
    asm("mov.b64 {%0, %1}, %2;" : "=f"(lo), "=f"(hi) : "l"(a));
}

// ---------------------------------------------------------------------------
// Kernel 1: s[n,ci] = style[n,:] . style_w[ci,:] + style_b[ci]
// ---------------------------------------------------------------------------
__global__ void k_style(const float* __restrict__ style,
                        const float* __restrict__ style_w,
                        const float* __restrict__ style_b)
{
    int idx = blockIdx.x * blockDim.x + threadIdx.x;   // NB*CIN = 8192
    if (idx >= NB*CIN) return;
    int n  = idx >> 9;
    int ci = idx & 511;
    const float* st = style   + n  * STY;
    const float* sw = style_w + ci * STY;
    float acc = 0.f;
    #pragma unroll 8
    for (int k = 0; k < STY; ++k) acc += st[k] * sw[k];
    g_s[idx] = acc + style_b[ci];
}

// ---------------------------------------------------------------------------
// Kernel 2: wsq[co,ci] = sum over 9 taps of weight^2, and weight transpose
//           g_wt[ci][tap][co] = weight[co][ci][tap]
// ---------------------------------------------------------------------------
__global__ void k_wsq(const float* __restrict__ weight)
{
    int idx = blockIdx.x * blockDim.x + threadIdx.x;   // COUT*CIN = 262144
    if (idx >= COUT*CIN) return;
    int co = idx >> 9;
    int ci = idx & 511;
    const float* w = weight + (size_t)idx * KT;
    float acc = 0.f;
    #pragma unroll
    for (int k = 0; k < KT; ++k) {
        float v = w[k];
        acc += v * v;
        g_wt[((size_t)ci * KT + k) * COUT + co] = v;
    }
    g_wsq[idx] = acc;
}

// ---------------------------------------------------------------------------
// Kernel 3: demod[n,co] = rsqrt( sum_ci s[n,ci]^2 * wsq[co,ci] + eps )
// ---------------------------------------------------------------------------
__global__ void k_demod()
{
    int idx = blockIdx.x * blockDim.x + threadIdx.x;   // NB*COUT = 8192
    if (idx >= NB*COUT) return;
    int n  = idx >> 9;
    int co = idx & 511;
    const float* sp = g_s   + n  * CIN;
    const float* wq = g_wsq + co * CIN;
    float acc = 0.f;
    #pragma unroll 8
    for (int ci = 0; ci < CIN; ++ci) {
        float sv = sp[ci];
        acc += sv * sv * wq[ci];
    }
    g_demod[idx] = rsqrtf(acc + 1e-8f);
}

// ---------------------------------------------------------------------------
// Kernel 4: shared-weight conv, f32x2-packed along co.
// Block tile: 128 co x 64 pixels (one output row h). 256 threads.
// Thread tile: 8 co (4 packed pairs) x 4 pixels.
// ---------------------------------------------------------------------------
#define CK 8
#define XW 68   // padded row width (cols 0..65 valid), mult of 4 for float4
#define WSW 132 // padded co row width, mult of 4

__global__ __launch_bounds__(256, 3) void k_conv(
    const float* __restrict__ x,
    const float* __restrict__ noise,
    const float* __restrict__ noise_w,
    float* __restrict__ out)
{
    __shared__ float xs[CK][3][XW];       // x rows h-1..h+1, cols -1..64
    __shared__ float ws[CK][KT][WSW];     // weights [ci][tap][co_l]

    const int n   = blockIdx.z;
    const int co0 = blockIdx.y * 128;
    const int h   = blockIdx.x;
    const int tid = threadIdx.x;
    const int tx  = tid & 15;      // pixel group: cols tx*4 .. tx*4+3
    const int ty  = tid >> 4;      // co group:    co0 + ty*8 .. +7

    u64 acc2[4][4];                // [co_pair][pixel]
    #pragma unroll
    for (int p = 0; p < 4; ++p)
        #pragma unroll
        for (int j = 0; j < 4; ++j) acc2[p][j] = 0ull;

    const float* xn = x + (size_t)n * CIN * HW;
    const float* sn = g_s + n * CIN;
    const float4* wt4 = (const float4*)g_wt;

    for (int ci0 = 0; ci0 < CIN; ci0 += CK) {
        __syncthreads();

        // ---- stage x (halo + zero pad), folding in s[n,ci] ----
        for (int i = tid; i < CK*3*66; i += 256) {
            int ci  = i / 198;
            int rem = i - ci * 198;
            int r   = rem / 66;
            int c   = rem - r * 66;
            int hr  = h - 1 + r;
            int col = c - 1;
            float v = 0.f;
            if ((unsigned)hr < (unsigned)HH && (unsigned)col < (unsigned)WW)
                v = xn[(size_t)(ci0 + ci) * HW + hr * WW + col] * sn[ci0 + ci];
            xs[ci][r][c] = v;
        }

        // ---- stage weights from pre-transposed g_wt: LDG.128 -> STS.128 ----
        // row = ci*9+tap (72 rows), 32 float4 per row
        for (int i = tid; i < CK*KT*32; i += 256) {
            int row = i >> 5;
            int c4  = i & 31;
            float4 v = wt4[(size_t)(ci0*KT + row) * (COUT/4) + (co0 >> 2) + c4];
            int ci  = row / 9;
            int tap = row - ci * 9;
            *(float4*)&ws[ci][tap][c4 * 4] = v;
        }

        __syncthreads();

        // ---- compute (packed f32x2 along co) ----
        #pragma unroll
        for (int ci = 0; ci < CK; ++ci) {
            #pragma unroll
            for (int kh = 0; kh < 3; ++kh) {
                const float* xrow = &xs[ci][kh][tx * 4];
                float4 xa = *(const float4*)xrow;
                float2 xb = *(const float2*)(xrow + 4);
                u64 xx[6];
                xx[0] = pk2(xa.x); xx[1] = pk2(xa.y); xx[2] = pk2(xa.z);
                xx[3] = pk2(xa.w); xx[4] = pk2(xb.x); xx[5] = pk2(xb.y);
                #pragma unroll
                for (int kw = 0; kw < 3; ++kw) {
                    const u64* wrow = (const u64*)&ws[ci][kh*3 + kw][ty * 8];
                    ulonglong2 wA = *(const ulonglong2*)wrow;        // co pairs 0,1
                    ulonglong2 wB = *(const ulonglong2*)(wrow + 2);  // co pairs 2,3
                    u64 wp0 = wA.x, wp1 = wA.y, wp2 = wB.x, wp3 = wB.y;
                    #pragma unroll
                    for (int j = 0; j < 4; ++j) {
                        acc2[0][j] = ffma2(wp0, xx[kw + j], acc2[0][j]);
                        acc2[1][j] = ffma2(wp1, xx[kw + j], acc2[1][j]);
                        acc2[2][j] = ffma2(wp2, xx[kw + j], acc2[2][j]);
                        acc2[3][j] = ffma2(wp3, xx[kw + j], acc2[3][j]);
                    }
                }
            }
        }
    }

    // ---- epilogue: demod, noise injection, LeakyReLU(0.2) ----
    const float nw = noise_w[0];
    float nz[4];
    #pragma unroll
    for (int j = 0; j < 4; ++j)
        nz[j] = nw * noise[(size_t)n * HW + h * WW + tx*4 + j];

    #pragma unroll
    for (int p = 0; p < 4; ++p) {
        int co_a = co0 + ty*8 + 2*p;
        float da = g_demod[n * COUT + co_a];
        float db = g_demod[n * COUT + co_a + 1];
        #pragma unroll
        for (int j = 0; j < 4; ++j) {
            float lo, hi;
            unpk2(acc2[p][j], lo, hi);
            float va = lo * da + nz[j];
            float vb = hi * db + nz[j];
            va = (va >= 0.f) ? va : 0.2f * va;
            vb = (vb >= 0.f) ? vb : 0.2f * vb;
            int col = tx*4 + j;
            out[(((size_t)n * COUT + co_a    ) * HH + h) * WW + col] = va;
            out[(((size_t)n * COUT + co_a + 1) * HH + h) * WW + col] = vb;
        }
    }
}

// ---------------------------------------------------------------------------
// Launcher
// Inputs: x, style, noise, weight, style_w, style_b, noise_weight
// ---------------------------------------------------------------------------
extern "C" void kernel_launch(void* const* d_in, const int* in_sizes, int n_in,
                              void* d_out, int out_size)
{
    const float* x        = (const float*)d_in[0];
    const float* style    = (const float*)d_in[1];
    const float* noise    = (const float*)d_in[2];
    const float* weight   = (const float*)d_in[3];
    const float* style_w  = (const float*)d_in[4];
    const float* style_b  = (const float*)d_in[5];
    const float* noise_w  = (const float*)d_in[6];
    float* out            = (float*)d_out;

    k_style<<<(NB*CIN + 255)/256, 256>>>(style, style_w, style_b);
    k_wsq<<<(COUT*CIN + 255)/256, 256>>>(weight);
    k_demod<<<(NB*COUT + 255)/256, 256>>>();

    dim3 grid(HH, COUT/128, NB);   // 64 x 4 x 16 = 4096 blocks
    k_conv<<<grid, 256>>>(x, noise, noise_w, out);
}

// round 9
// speedup vs baseline: 3.1927x; 3.1927x over previous
#include <cuda_runtime.h>
#include <cuda_bf16.h>
#include <math.h>
#include <stdint.h>

// ---------------- problem constants ----------------
#define NB   16
#define CIN  512
#define COUT 512
#define HH   64
#define WW   64
#define HW   (HH*WW)
#define STY  512
#define KT   9
#define XP   4356          // padded pixels per sample: 66*66

// ---------------- scratch (device globals) ----------------
__device__ float g_s[NB*CIN];
__device__ float g_wsq[COUT*CIN];
__device__ float g_demod[NB*COUT];
// modulated x, bf16 hi/lo, transposed+padded: [n][P=(h+1)*66+(w+1)][ci]
__device__ __nv_bfloat16 g_xh[(size_t)NB*XP*CIN];
__device__ __nv_bfloat16 g_xl[(size_t)NB*XP*CIN];
// weights bf16 hi/lo, transposed: [tap][co][ci]
__device__ __nv_bfloat16 g_wh[(size_t)KT*COUT*CIN];
__device__ __nv_bfloat16 g_wl[(size_t)KT*COUT*CIN];

// ---------------- PTX helpers (sm_103 baseline features only) -------------
__device__ __forceinline__ uint32_t smem_u32(const void* p) {
    uint32_t a;
    asm("{ .reg .u64 t; cvta.to.shared.u64 t, %1; cvt.u32.u64 %0, t; }"
        : "=r"(a) : "l"(p));
    return a;
}
__device__ __forceinline__ void cp16(uint32_t dst, const void* src) {
    asm volatile("cp.async.cg.shared.global [%0], [%1], 16;"
                 :: "r"(dst), "l"(src) : "memory");
}
#define CP_COMMIT() asm volatile("cp.async.commit_group;" ::: "memory")
#define CP_WAIT1()  asm volatile("cp.async.wait_group 1;" ::: "memory")
#define CP_WAIT0()  asm volatile("cp.async.wait_group 0;" ::: "memory")

__device__ __forceinline__ void ldm_x4(uint32_t* r, uint32_t addr) {
    asm volatile("ldmatrix.sync.aligned.m8n8.x4.shared.b16 {%0,%1,%2,%3}, [%4];"
        : "=r"(r[0]), "=r"(r[1]), "=r"(r[2]), "=r"(r[3]) : "r"(addr));
}
__device__ __forceinline__ void mma16816(float* c, const uint32_t* a, const uint32_t* b) {
    asm volatile(
        "mma.sync.aligned.m16n8k16.row.col.f32.bf16.bf16.f32 "
        "{%0,%1,%2,%3}, {%4,%5,%6,%7}, {%8,%9}, {%0,%1,%2,%3};"
        : "+f"(c[0]), "+f"(c[1]), "+f"(c[2]), "+f"(c[3])
        : "r"(a[0]), "r"(a[1]), "r"(a[2]), "r"(a[3]), "r"(b[0]), "r"(b[1]));
}

// ---------------- prologue kernels ----------------
__global__ void k_style(const float* __restrict__ style,
                        const float* __restrict__ style_w,
                        const float* __restrict__ style_b)
{
    int idx = blockIdx.x * blockDim.x + threadIdx.x;
    if (idx >= NB*CIN) return;
    int n = idx >> 9, ci = idx & 511;
    const float* st = style + n * STY;
    const float* sw = style_w + ci * STY;
    float acc = 0.f;
    #pragma unroll 8
    for (int k = 0; k < STY; ++k) acc += st[k] * sw[k];
    g_s[idx] = acc + style_b[ci];
}

// wsq + bf16 hi/lo weight transpose to [tap][co][ci]
__global__ void k_wprep(const float* __restrict__ weight)
{
    int idx = blockIdx.x * blockDim.x + threadIdx.x;   // COUT*CIN
    if (idx >= COUT*CIN) return;
    int co = idx >> 9, ci = idx & 511;
    const float* w = weight + (size_t)idx * KT;
    float acc = 0.f;
    #pragma unroll
    for (int tap = 0; tap < KT; ++tap) {
        float v = w[tap];
        acc += v * v;
        __nv_bfloat16 hb = __float2bfloat16(v);
        float hf = __bfloat162float(hb);
        __nv_bfloat16 lb = __float2bfloat16(v - hf);
        size_t o = ((size_t)tap * COUT + co) * CIN + ci;
        g_wh[o] = hb;
        g_wl[o] = lb;
    }
    g_wsq[idx] = acc;
}

__global__ void k_demod()
{
    int idx = blockIdx.x * blockDim.x + threadIdx.x;
    if (idx >= NB*COUT) return;
    int n = idx >> 9, co = idx & 511;
    const float* sp = g_s + n * CIN;
    const float* wq = g_wsq + co * CIN;
    float acc = 0.f;
    #pragma unroll 8
    for (int ci = 0; ci < CIN; ++ci) { float sv = sp[ci]; acc += sv * sv * wq[ci]; }
    g_demod[idx] = rsqrtf(acc + 1e-8f);
}

__global__ void k_xzero()
{
    size_t total = (size_t)NB * XP * CIN / 8;   // uint4 units per array
    uint4 z = make_uint4(0,0,0,0);
    uint4* a = (uint4*)g_xh;
    uint4* b = (uint4*)g_xl;
    for (size_t i = blockIdx.x * (size_t)blockDim.x + threadIdx.x; i < total;
         i += (size_t)gridDim.x * blockDim.x) { a[i] = z; b[i] = z; }
}

// modulate + bf16 split + transpose to [P][ci]
__global__ void k_xprep(const float* __restrict__ x)
{
    __shared__ float s[32][33];
    int p0  = blockIdx.x * 32;
    int ci0 = blockIdx.y * 32;
    int n   = blockIdx.z;
    int tx = threadIdx.x, ty = threadIdx.y;   // 32 x 8

    #pragma unroll
    for (int k = 0; k < 4; ++k) {
        int ci = ci0 + ty + k*8;
        float v = x[((size_t)(n*CIN + ci)) * HW + p0 + tx] * g_s[n*CIN + ci];
        s[tx][ty + k*8] = v;     // s[pix_local][ci_local]
    }
    __syncthreads();
    #pragma unroll
    for (int k = 0; k < 4; ++k) {
        int pl = ty + k*8;
        int p  = p0 + pl;
        int h  = p >> 6, w = p & 63;
        size_t P = (size_t)(h + 1) * 66 + (w + 1);
        float v = s[pl][tx];
        __nv_bfloat16 hb = __float2bfloat16(v);
        float hf = __bfloat162float(hb);
        __nv_bfloat16 lb = __float2bfloat16(v - hf);
        size_t o = ((size_t)n * XP + P) * CIN + ci0 + tx;
        g_xh[o] = hb;
        g_xl[o] = lb;
    }
}

// ---------------- main MMA conv ----------------
// Static smem: 2 buffers x 4 parts (Ah, Al, Bh, Bl) x 128 rows x 48B = 49152B.
// Row pitch 48B keeps ldmatrix conflict-free (48*i mod 128 distinct for 8 rows).
#define PITCH 48
#define PART  6144          // 128*48
#define STAGEB 24576        // 4 parts
#define NSTAGE 288          // 9 taps * 32 ci-chunks of 16

__global__ void __launch_bounds__(256) k_conv_mma(
    const float* __restrict__ noise,
    const float* __restrict__ noise_w,
    float* __restrict__ out)
{
    __shared__ __align__(128) char smem[2*STAGEB];
    const uint32_t sb = smem_u32(smem);

    const int tid = threadIdx.x;
    const int lane = tid & 31, wid = tid >> 5;
    const int warp_m = wid >> 2;          // 0..1  (64 co each)
    const int warp_n = wid & 3;           // 0..3  (32 pix each)

    const int pb  = blockIdx.x;           // 32 pixel blocks (128 pix = 2 rows)
    const int co0 = blockIdx.y << 7;      // 4 co blocks
    const int n   = blockIdx.z;           // 16 samples
    const int p0  = pb << 7;
    const int h0  = pb << 1;

    // staging coords for this thread (same for all 4 parts)
    const int sr  = tid >> 1;             // row 0..127
    const int seg = tid & 1;              // 16B segment within 32B row
    const int bh_row = h0 + (sr >> 6);    // image row of B pixel (pre-tap)
    const int bw_col = sr & 63;

    float acc[4][4][4];
    #pragma unroll
    for (int mt = 0; mt < 4; ++mt)
        #pragma unroll
        for (int nt = 0; nt < 4; ++nt)
            #pragma unroll
            for (int q = 0; q < 4; ++q) acc[mt][nt][q] = 0.f;

    // fragment smem addresses (fixed per thread)
    const uint32_t a_row = warp_m*64 + (lane & 7) + ((lane >> 3) & 1) * 8;
    const uint32_t a_col = ((lane >> 4) & 1) * 16;
    const uint32_t b_row = warp_n*32 + (lane & 7) + ((lane >> 4) & 1) * 8;
    const uint32_t b_col = ((lane >> 3) & 1) * 16;

    // ---- stage 0 load ----
    {
        const int tap = 0, ci0 = 0;
        const int kh = 0, kw = 0;
        size_t ao = ((size_t)(tap*COUT + co0 + sr))*CIN + ci0 + seg*8;
        size_t bo = ((size_t)n*XP + (size_t)(bh_row + kh)*66 + (bw_col + kw))*CIN + ci0 + seg*8;
        uint32_t db = sb + sr*PITCH + seg*16;
        cp16(db,            g_wh + ao);
        cp16(db + PART,     g_wl + ao);
        cp16(db + 2*PART,   g_xh + bo);
        cp16(db + 3*PART,   g_xl + bo);
        CP_COMMIT();
    }

    for (int s = 0; s < NSTAGE; ++s) {
        if (s + 1 < NSTAGE) {
            const int s1 = s + 1;
            const int tap = s1 >> 5;
            const int ci0 = (s1 & 31) << 4;
            const int kh = tap / 3, kw = tap - kh*3;
            size_t ao = ((size_t)(tap*COUT + co0 + sr))*CIN + ci0 + seg*8;
            size_t bo = ((size_t)n*XP + (size_t)(bh_row + kh)*66 + (bw_col + kw))*CIN + ci0 + seg*8;
            uint32_t db = sb + (s1 & 1)*STAGEB + sr*PITCH + seg*16;
            cp16(db,            g_wh + ao);
            cp16(db + PART,     g_wl + ao);
            cp16(db + 2*PART,   g_xh + bo);
            cp16(db + 3*PART,   g_xl + bo);
            CP_COMMIT();
            CP_WAIT1();
        } else {
            CP_WAIT0();
        }
        __syncthreads();

        const uint32_t base = sb + (s & 1)*STAGEB;
        uint32_t ah[4][4], al[4][4], bh[2][4], bl[2][4];
        #pragma unroll
        for (int mt = 0; mt < 4; ++mt) {
            uint32_t ad = base + (a_row + mt*16)*PITCH + a_col;
            ldm_x4(ah[mt], ad);
            ldm_x4(al[mt], ad + PART);
        }
        #pragma unroll
        for (int jp = 0; jp < 2; ++jp) {
            uint32_t bd = base + 2*PART + (b_row + jp*16)*PITCH + b_col;
            ldm_x4(bh[jp], bd);
            ldm_x4(bl[jp], bd + PART);
        }
        #pragma unroll
        for (int mt = 0; mt < 4; ++mt)
            #pragma unroll
            for (int nt = 0; nt < 4; ++nt) {
                const uint32_t* bhp = &bh[nt >> 1][(nt & 1) * 2];
                const uint32_t* blp = &bl[nt >> 1][(nt & 1) * 2];
                mma16816(acc[mt][nt], ah[mt], bhp);   // Wh * Xh
                mma16816(acc[mt][nt], al[mt], bhp);   // Wl * Xh
                mma16816(acc[mt][nt], ah[mt], blp);   // Wh * Xl
            }
        __syncthreads();
    }

    // ---- epilogue: demod + noise + LeakyReLU ----
    const float nw = noise_w[0];
    const int g  = lane >> 2;
    const int tg = lane & 3;
    #pragma unroll
    for (int mt = 0; mt < 4; ++mt) {
        int co = co0 + warp_m*64 + mt*16 + g;
        float d0 = g_demod[(n << 9) + co];
        float d1 = g_demod[(n << 9) + co + 8];
        #pragma unroll
        for (int nt = 0; nt < 4; ++nt) {
            int px = p0 + warp_n*32 + nt*8 + tg*2;
            float nz0 = nw * noise[(size_t)n*HW + px];
            float nz1 = nw * noise[(size_t)n*HW + px + 1];
            float v0 = acc[mt][nt][0] * d0 + nz0;
            float v1 = acc[mt][nt][1] * d0 + nz1;
            float v2 = acc[mt][nt][2] * d1 + nz0;
            float v3 = acc[mt][nt][3] * d1 + nz1;
            v0 = (v0 >= 0.f) ? v0 : 0.2f*v0;
            v1 = (v1 >= 0.f) ? v1 : 0.2f*v1;
            v2 = (v2 >= 0.f) ? v2 : 0.2f*v2;
            v3 = (v3 >= 0.f) ? v3 : 0.2f*v3;
            float2 r0 = make_float2(v0, v1);
            float2 r1 = make_float2(v2, v3);
            *(float2*)(out + (((size_t)n*COUT + co    ) << 12) + px) = r0;
            *(float2*)(out + (((size_t)n*COUT + co + 8) << 12) + px) = r1;
        }
    }
}

// ---------------- launcher ----------------
extern "C" void kernel_launch(void* const* d_in, const int* in_sizes, int n_in,
                              void* d_out, int out_size)
{
    const float* x       = (const float*)d_in[0];
    const float* style   = (const float*)d_in[1];
    const float* noise   = (const float*)d_in[2];
    const float* weight  = (const float*)d_in[3];
    const float* style_w = (const float*)d_in[4];
    const float* style_b = (const float*)d_in[5];
    const float* noise_w = (const float*)d_in[6];
    float* out           = (float*)d_out;

    k_style<<<(NB*CIN + 255)/256, 256>>>(style, style_w, style_b);
    k_wprep<<<(COUT*CIN + 255)/256, 256>>>(weight);
    k_demod<<<(NB*COUT + 255)/256, 256>>>();
    k_xzero<<<2048, 256>>>();
    {
        dim3 grid(HW/32, CIN/32, NB);
        dim3 block(32, 8);
        k_xprep<<<grid, block>>>(x);
    }
    {
        dim3 grid(HW/128, COUT/128, NB);   // 32 x 4 x 16 = 2048 blocks
        k_conv_mma<<<grid, 256>>>(noise, noise_w, out);
    }
}

// round 12
// speedup vs baseline: 4.5245x; 1.4171x over previous
#include <cuda_runtime.h>
#include <cuda_fp16.h>
#include <math.h>
#include <stdint.h>

// ---------------- problem constants ----------------
#define NB   16
#define CIN  512
#define COUT 512
#define HH   64
#define WW   64
#define HW   (HH*WW)
#define STY  512
#define KT   9
#define XP   4356          // padded pixels per sample: 66*66

// ---------------- scratch (device globals) ----------------
__device__ float g_s[NB*CIN];
__device__ float g_wsq[COUT*CIN];
__device__ float g_demod[NB*COUT];
// modulated x, fp16 hi/lo split, transposed+padded: [n][P=(h+1)*66+(w+1)][ci]
__device__ __half g_xh[(size_t)NB*XP*CIN];
__device__ __half g_xl[(size_t)NB*XP*CIN];
// weights fp16, transposed: [tap][co][ci]
__device__ __half g_wh[(size_t)KT*COUT*CIN];

// ---------------- PTX helpers ----------------
__device__ __forceinline__ uint32_t smem_u32(const void* p) {
    uint32_t a;
    asm("{ .reg .u64 t; cvta.to.shared.u64 t, %1; cvt.u32.u64 %0, t; }"
        : "=r"(a) : "l"(p));
    return a;
}
__device__ __forceinline__ void cp16(uint32_t dst, const void* src) {
    asm volatile("cp.async.cg.shared.global [%0], [%1], 16;"
                 :: "r"(dst), "l"(src) : "memory");
}
#define CP_COMMIT() asm volatile("cp.async.commit_group;" ::: "memory")
#define CP_WAIT1()  asm volatile("cp.async.wait_group 1;" ::: "memory")
#define CP_WAIT0()  asm volatile("cp.async.wait_group 0;" ::: "memory")

__device__ __forceinline__ void ldm_x4(uint32_t* r, uint32_t addr) {
    asm volatile("ldmatrix.sync.aligned.m8n8.x4.shared.b16 {%0,%1,%2,%3}, [%4];"
        : "=r"(r[0]), "=r"(r[1]), "=r"(r[2]), "=r"(r[3]) : "r"(addr));
}
__device__ __forceinline__ void mma16816(float* c, const uint32_t* a, const uint32_t* b) {
    asm volatile(
        "mma.sync.aligned.m16n8k16.row.col.f32.f16.f16.f32 "
        "{%0,%1,%2,%3}, {%4,%5,%6,%7}, {%8,%9}, {%0,%1,%2,%3};"
        : "+f"(c[0]), "+f"(c[1]), "+f"(c[2]), "+f"(c[3])
        : "r"(a[0]), "r"(a[1]), "r"(a[2]), "r"(a[3]), "r"(b[0]), "r"(b[1]));
}

// ---------------- prologue kernels ----------------
__global__ void k_style(const float* __restrict__ style,
                        const float* __restrict__ style_w,
                        const float* __restrict__ style_b)
{
    int idx = blockIdx.x * blockDim.x + threadIdx.x;
    if (idx >= NB*CIN) return;
    int n = idx >> 9, ci = idx & 511;
    const float* st = style + n * STY;
    const float* sw = style_w + ci * STY;
    float acc = 0.f;
    #pragma unroll 8
    for (int k = 0; k < STY; ++k) acc += st[k] * sw[k];
    g_s[idx] = acc + style_b[ci];
}

// wsq + fp16 weight transpose to [tap][co][ci]
__global__ void k_wprep(const float* __restrict__ weight)
{
    int idx = blockIdx.x * blockDim.x + threadIdx.x;   // COUT*CIN
    if (idx >= COUT*CIN) return;
    int co = idx >> 9, ci = idx & 511;
    const float* w = weight + (size_t)idx * KT;
    float acc = 0.f;
    #pragma unroll
    for (int tap = 0; tap < KT; ++tap) {
        float v = w[tap];
        acc += v * v;
        g_wh[((size_t)tap * COUT + co) * CIN + ci] = __float2half(v);
    }
    g_wsq[idx] = acc;
}

__global__ void k_demod()
{
    int idx = blockIdx.x * blockDim.x + threadIdx.x;
    if (idx >= NB*COUT) return;
    int n = idx >> 9, co = idx & 511;
    const float* sp = g_s + n * CIN;
    const float* wq = g_wsq + co * CIN;
    float acc = 0.f;
    #pragma unroll 8
    for (int ci = 0; ci < CIN; ++ci) { float sv = sp[ci]; acc += sv * sv * wq[ci]; }
    g_demod[idx] = rsqrtf(acc + 1e-8f);
}

// zero only the 260 border pixel-rows per sample (interior written by k_xprep)
__global__ void k_xzero_border()
{
    // units: [n][border(260)][ci_vec(64)]; each writes 16B in both arrays
    int idx = blockIdx.x * blockDim.x + threadIdx.x;
    if (idx >= NB*260*64) return;
    int cv = idx & 63;
    int b  = (idx >> 6) % 260;
    int n  = idx / (260*64);
    int P;
    if (b < 66)       P = b;                       // top row
    else if (b < 132) P = 65*66 + (b - 66);        // bottom row
    else if (b < 196) P = (b - 132 + 1)*66;        // left col (rows 1..64)
    else              P = (b - 196 + 1)*66 + 65;   // right col
    size_t o = (((size_t)n * XP + P) * CIN) + cv*8;
    uint4 z = make_uint4(0,0,0,0);
    *(uint4*)(g_xh + o) = z;
    *(uint4*)(g_xl + o) = z;
}

// modulate + fp16 split + transpose to [P][ci]
__global__ void k_xprep(const float* __restrict__ x)
{
    __shared__ float s[32][33];
    int p0  = blockIdx.x * 32;
    int ci0 = blockIdx.y * 32;
    int n   = blockIdx.z;
    int tx = threadIdx.x, ty = threadIdx.y;   // 32 x 8

    #pragma unroll
    for (int k = 0; k < 4; ++k) {
        int ci = ci0 + ty + k*8;
        float v = x[((size_t)(n*CIN + ci)) * HW + p0 + tx] * g_s[n*CIN + ci];
        s[tx][ty + k*8] = v;
    }
    __syncthreads();
    #pragma unroll
    for (int k = 0; k < 4; ++k) {
        int pl = ty + k*8;
        int p  = p0 + pl;
        int h  = p >> 6, w = p & 63;
        size_t P = (size_t)(h + 1) * 66 + (w + 1);
        float v = s[pl][tx];
        __half hb = __float2half(v);
        float hf = __half2float(hb);
        __half lb = __float2half(v - hf);
        size_t o = ((size_t)n * XP + P) * CIN + ci0 + tx;
        g_xh[o] = hb;
        g_xl[o] = lb;
    }
}

// ---------------- main MMA conv ----------------
// smem: X double buffer 2x16896 (hi 8448 | lo 8448), A double buffer 2x4096.
// X chunk: 264 pixel-rows (4 padded rows x 66 cols) x 32B (16 ci fp16).
#define XBUF 16896
#define XHALF 8448
#define ABUF 4096
#define SM_X 0
#define SM_A (2*XBUF)          // 33792
#define SMEM_BYTES (2*XBUF + 2*ABUF)   // 41984

__global__ void __launch_bounds__(256) k_conv_mma(
    const float* __restrict__ noise,
    const float* __restrict__ noise_w,
    float* __restrict__ out)
{
    __shared__ __align__(128) char smem[SMEM_BYTES];
    const uint32_t sb = smem_u32(smem);
    const uint32_t sbX = sb + SM_X;
    const uint32_t sbA = sb + SM_A;

    const int tid = threadIdx.x;
    const int lane = tid & 31, wid = tid >> 5;
    const int warp_m = wid >> 2;          // 0..1  (64 co)
    const int warp_n = wid & 3;           // 0..3  (32 px)

    const int pb  = blockIdx.x;           // 32 pixel blocks (128 px = 2 rows)
    const int co0 = blockIdx.y << 7;
    const int n   = blockIdx.z;
    const int p0  = pb << 7;
    const int h0  = pb << 1;              // padded rows h0..h0+3 needed

    // A staging coords
    const int arow = tid >> 1;
    const int aseg = tid & 1;

    // A fragment address components
    const uint32_t a_row = warp_m*64 + (lane & 7) + ((lane >> 3) & 1) * 8;
    const uint32_t a_col = ((lane >> 4) & 1) * 16;

    // B per-lane fixed pixel offsets (two jp halves)
    uint32_t pixoff[2];
    {
        int khalf = (lane >> 3) & 1;
        #pragma unroll
        for (int jp = 0; jp < 2; ++jp) {
            int px = warp_n*32 + (lane & 7) + ((lane >> 4) & 1)*8 + jp*16;
            int dt = px >> 6, col = px & 63;
            pixoff[jp] = (uint32_t)(dt*66 + col)*32 + khalf*16;
        }
    }

    float acc[4][4][4];
    #pragma unroll
    for (int mt = 0; mt < 4; ++mt)
        #pragma unroll
        for (int nt = 0; nt < 4; ++nt)
            #pragma unroll
            for (int q = 0; q < 4; ++q) acc[mt][nt][q] = 0.f;

    // ---- staging lambdas (macros) ----
    // stage X for chunk ck into buffer ck&1
    #define STAGE_X(ck) do {                                                 \
        int ciN = (ck) << 4;                                                 \
        uint32_t xd = sbX + ((ck) & 1) * XBUF;                               \
        for (int i = tid; i < 1056; i += 256) {                              \
            int ver = i >= 528;                                              \
            int j   = i - ver*528;                                           \
            int row = j >> 1, seg = j & 1;                                   \
            int pr  = row / 66, pc = row - pr*66;                            \
            size_t so = ((size_t)n*XP + (size_t)(h0 + pr)*66 + pc)*CIN + ciN + seg*8; \
            const __half* sp = ver ? g_xl : g_xh;                            \
            cp16(xd + ver*XHALF + row*32 + seg*16, sp + so);                 \
        }                                                                    \
    } while (0)
    // stage A for (ck, tap) into buffer s&1
    #define STAGE_A(s, ck, tap) do {                                         \
        size_t ao = ((size_t)((tap)*COUT + co0 + arow))*CIN + ((ck) << 4) + aseg*8; \
        cp16(sbA + ((s) & 1)*ABUF + arow*32 + aseg*16, g_wh + ao);           \
    } while (0)

    // prologue: X chunk 0 + A stage 0
    STAGE_X(0);
    STAGE_A(0, 0, 0);
    CP_COMMIT();

    for (int ck = 0; ck < 32; ++ck) {
        #pragma unroll 1
        for (int tap = 0; tap < 9; ++tap) {
            const int s = ck*9 + tap;
            // prefetch next stage
            if (s + 1 < 288) {
                int tapN = (tap == 8) ? 0 : tap + 1;
                int ckN  = (tap == 8) ? ck + 1 : ck;
                STAGE_A(s + 1, ckN, tapN);
            }
            if (tap == 0 && ck + 1 < 32) STAGE_X(ck + 1);
            CP_COMMIT();
            if (s + 1 < 288) CP_WAIT1(); else CP_WAIT0();
            __syncthreads();

            // ---- fragments ----
            const uint32_t ab = sbA + (s & 1)*ABUF;
            uint32_t a[4][4];
            #pragma unroll
            for (int mt = 0; mt < 4; ++mt)
                ldm_x4(a[mt], ab + (a_row + mt*16)*32 + a_col);

            const int kh = tap / 3;
            const int kw = tap - kh*3;
            const uint32_t xb = sbX + (ck & 1)*XBUF + (uint32_t)(kh*66 + kw)*32;
            uint32_t bh[2][4], bl[2][4];
            #pragma unroll
            for (int jp = 0; jp < 2; ++jp) {
                ldm_x4(bh[jp], xb + pixoff[jp]);
                ldm_x4(bl[jp], xb + pixoff[jp] + XHALF);
            }

            // ---- mma: W*Xh then W*Xl (both into acc) ----
            #pragma unroll
            for (int mt = 0; mt < 4; ++mt)
                #pragma unroll
                for (int nt = 0; nt < 4; ++nt)
                    mma16816(acc[mt][nt], a[mt], &bh[nt >> 1][(nt & 1)*2]);
            #pragma unroll
            for (int mt = 0; mt < 4; ++mt)
                #pragma unroll
                for (int nt = 0; nt < 4; ++nt)
                    mma16816(acc[mt][nt], a[mt], &bl[nt >> 1][(nt & 1)*2]);
            __syncthreads();
        }
    }

    // ---- epilogue: demod + noise + LeakyReLU ----
    const float nw = noise_w[0];
    const int g  = lane >> 2;
    const int tg = lane & 3;
    #pragma unroll
    for (int mt = 0; mt < 4; ++mt) {
        int co = co0 + warp_m*64 + mt*16 + g;
        float d0 = g_demod[(n << 9) + co];
        float d1 = g_demod[(n << 9) + co + 8];
        #pragma unroll
        for (int nt = 0; nt < 4; ++nt) {
            int px = p0 + warp_n*32 + nt*8 + tg*2;
            float nz0 = nw * noise[(size_t)n*HW + px];
            float nz1 = nw * noise[(size_t)n*HW + px + 1];
            float v0 = acc[mt][nt][0] * d0 + nz0;
            float v1 = acc[mt][nt][1] * d0 + nz1;
            float v2 = acc[mt][nt][2] * d1 + nz0;
            float v3 = acc[mt][nt][3] * d1 + nz1;
            v0 = (v0 >= 0.f) ? v0 : 0.2f*v0;
            v1 = (v1 >= 0.f) ? v1 : 0.2f*v1;
            v2 = (v2 >= 0.f) ? v2 : 0.2f*v2;
            v3 = (v3 >= 0.f) ? v3 : 0.2f*v3;
            *(float2*)(out + (((size_t)n*COUT + co    ) << 12) + px) = make_float2(v0, v1);
            *(float2*)(out + (((size_t)n*COUT + co + 8) << 12) + px) = make_float2(v2, v3);
        }
    }
}

// ---------------- launcher ----------------
extern "C" void kernel_launch(void* const* d_in, const int* in_sizes, int n_in,
                              void* d_out, int out_size)
{
    const float* x       = (const float*)d_in[0];
    const float* style   = (const float*)d_in[1];
    const float* noise   = (const float*)d_in[2];
    const float* weight  = (const float*)d_in[3];
    const float* style_w = (const float*)d_in[4];
    const float* style_b = (const float*)d_in[5];
    const float* noise_w = (const float*)d_in[6];
    float* out           = (float*)d_out;

    k_style<<<(NB*CIN + 255)/256, 256>>>(style, style_w, style_b);
    k_wprep<<<(COUT*CIN + 255)/256, 256>>>(weight);
    k_demod<<<(NB*COUT + 255)/256, 256>>>();
    k_xzero_border<<<(NB*260*64 + 255)/256, 256>>>();
    {
        dim3 grid(HW/32, CIN/32, NB);
        dim3 block(32, 8);
        k_xprep<<<grid, block>>>(x);
    }
    {
        dim3 grid(HW/128, COUT/128, NB);   // 32 x 4 x 16 = 2048 blocks
        k_conv_mma<<<grid, 256>>>(noise, noise_w, out);
    }
}

// round 13
// speedup vs baseline: 6.4780x; 1.4318x over previous
#include <cuda_runtime.h>
#include <cuda_fp16.h>
#include <math.h>
#include <stdint.h>

// ---------------- problem constants ----------------
#define NB   16
#define CIN  512
#define COUT 512
#define HH   64
#define WW   64
#define HW   (HH*WW)
#define STY  512
#define KT   9
#define XP   4356          // padded pixels per sample: 66*66

// ---------------- scratch (device globals) ----------------
__device__ float g_s[NB*CIN];
__device__ float g_wsq[COUT*CIN];
__device__ float g_demod[NB*COUT];
// modulated x, fp16, transposed+padded: [n][P=(h+1)*66+(w+1)][ci]
__device__ __half g_xh[(size_t)NB*XP*CIN];
// weights fp16, transposed: [tap][co][ci]
__device__ __half g_wh[(size_t)KT*COUT*CIN];

// ---------------- PTX helpers ----------------
__device__ __forceinline__ uint32_t smem_u32(const void* p) {
    uint32_t a;
    asm("{ .reg .u64 t; cvta.to.shared.u64 t, %1; cvt.u32.u64 %0, t; }"
        : "=r"(a) : "l"(p));
    return a;
}
__device__ __forceinline__ void cp16(uint32_t dst, const void* src) {
    asm volatile("cp.async.cg.shared.global [%0], [%1], 16;"
                 :: "r"(dst), "l"(src) : "memory");
}
#define CP_COMMIT() asm volatile("cp.async.commit_group;" ::: "memory")
#define CP_WAIT1()  asm volatile("cp.async.wait_group 1;" ::: "memory")
#define CP_WAIT0()  asm volatile("cp.async.wait_group 0;" ::: "memory")

__device__ __forceinline__ void ldm_x4(uint32_t* r, uint32_t addr) {
    asm volatile("ldmatrix.sync.aligned.m8n8.x4.shared.b16 {%0,%1,%2,%3}, [%4];"
        : "=r"(r[0]), "=r"(r[1]), "=r"(r[2]), "=r"(r[3]) : "r"(addr));
}
__device__ __forceinline__ void mma16816(float* c, const uint32_t* a, const uint32_t* b) {
    asm volatile(
        "mma.sync.aligned.m16n8k16.row.col.f32.f16.f16.f32 "
        "{%0,%1,%2,%3}, {%4,%5,%6,%7}, {%8,%9}, {%0,%1,%2,%3};"
        : "+f"(c[0]), "+f"(c[1]), "+f"(c[2]), "+f"(c[3])
        : "r"(a[0]), "r"(a[1]), "r"(a[2]), "r"(a[3]), "r"(b[0]), "r"(b[1]));
}

// ---------------- prologue kernels ----------------
__global__ void k_style(const float* __restrict__ style,
                        const float* __restrict__ style_w,
                        const float* __restrict__ style_b)
{
    int idx = blockIdx.x * blockDim.x + threadIdx.x;
    if (idx >= NB*CIN) return;
    int n = idx >> 9, ci = idx & 511;
    const float* st = style + n * STY;
    const float* sw = style_w + ci * STY;
    float acc = 0.f;
    #pragma unroll 8
    for (int k = 0; k < STY; ++k) acc += st[k] * sw[k];
    g_s[idx] = acc + style_b[ci];
}

// wsq + fp16 weight transpose to [tap][co][ci]
__global__ void k_wprep(const float* __restrict__ weight)
{
    int idx = blockIdx.x * blockDim.x + threadIdx.x;   // COUT*CIN
    if (idx >= COUT*CIN) return;
    int co = idx >> 9, ci = idx & 511;
    const float* w = weight + (size_t)idx * KT;
    float acc = 0.f;
    #pragma unroll
    for (int tap = 0; tap < KT; ++tap) {
        float v = w[tap];
        acc += v * v;
        g_wh[((size_t)tap * COUT + co) * CIN + ci] = __float2half(v);
    }
    g_wsq[idx] = acc;
}

__global__ void k_demod()
{
    int idx = blockIdx.x * blockDim.x + threadIdx.x;
    if (idx >= NB*COUT) return;
    int n = idx >> 9, co = idx & 511;
    const float* sp = g_s + n * CIN;
    const float* wq = g_wsq + co * CIN;
    float acc = 0.f;
    #pragma unroll 8
    for (int ci = 0; ci < CIN; ++ci) { float sv = sp[ci]; acc += sv * sv * wq[ci]; }
    g_demod[idx] = rsqrtf(acc + 1e-8f);
}

// zero only the 260 border pixel-rows per sample
__global__ void k_xzero_border()
{
    int idx = blockIdx.x * blockDim.x + threadIdx.x;
    if (idx >= NB*260*64) return;
    int cv = idx & 63;
    int b  = (idx >> 6) % 260;
    int n  = idx / (260*64);
    int P;
    if (b < 66)       P = b;                       // top row
    else if (b < 132) P = 65*66 + (b - 66);        // bottom row
    else if (b < 196) P = (b - 132 + 1)*66;        // left col (rows 1..64)
    else              P = (b - 196 + 1)*66 + 65;   // right col
    size_t o = (((size_t)n * XP + P) * CIN) + cv*8;
    *(uint4*)(g_xh + o) = make_uint4(0,0,0,0);
}

// modulate + fp16 + transpose to [P][ci]
__global__ void k_xprep(const float* __restrict__ x)
{
    __shared__ float s[32][33];
    int p0  = blockIdx.x * 32;
    int ci0 = blockIdx.y * 32;
    int n   = blockIdx.z;
    int tx = threadIdx.x, ty = threadIdx.y;   // 32 x 8

    #pragma unroll
    for (int k = 0; k < 4; ++k) {
        int ci = ci0 + ty + k*8;
        float v = x[((size_t)(n*CIN + ci)) * HW + p0 + tx] * g_s[n*CIN + ci];
        s[tx][ty + k*8] = v;
    }
    __syncthreads();
    #pragma unroll
    for (int k = 0; k < 4; ++k) {
        int pl = ty + k*8;
        int p  = p0 + pl;
        int h  = p >> 6, w = p & 63;
        size_t P = (size_t)(h + 1) * 66 + (w + 1);
        size_t o = ((size_t)n * XP + P) * CIN + ci0 + tx;
        g_xh[o] = __float2half(s[pl][tx]);
    }
}

// ---------------- main MMA conv ----------------
// smem: X double buffer 2x8448, A double buffer 2x4096.
// X chunk: 264 pixel-rows (4 padded rows x 66 cols) x 32B (16 ci fp16).
#define XBUF 8448
#define ABUF 4096
#define SM_X 0
#define SM_A (2*XBUF)                  // 16896
#define SMEM_BYTES (2*XBUF + 2*ABUF)   // 25088

__global__ void __launch_bounds__(256) k_conv_mma(
    const float* __restrict__ noise,
    const float* __restrict__ noise_w,
    float* __restrict__ out)
{
    __shared__ __align__(128) char smem[SMEM_BYTES];
    const uint32_t sb = smem_u32(smem);
    const uint32_t sbX = sb + SM_X;
    const uint32_t sbA = sb + SM_A;

    const int tid = threadIdx.x;
    const int lane = tid & 31, wid = tid >> 5;
    const int warp_m = wid >> 2;          // 0..1  (64 co)
    const int warp_n = wid & 3;           // 0..3  (32 px)

    const int pb  = blockIdx.x;           // 32 pixel blocks (128 px = 2 rows)
    const int co0 = blockIdx.y << 7;
    const int n   = blockIdx.z;
    const int p0  = pb << 7;
    const int h0  = pb << 1;              // padded rows h0..h0+3 needed

    // A staging coords
    const int arow = tid >> 1;
    const int aseg = tid & 1;

    // A fragment address components
    const uint32_t a_row = warp_m*64 + (lane & 7) + ((lane >> 3) & 1) * 8;
    const uint32_t a_col = ((lane >> 4) & 1) * 16;

    // B per-lane fixed pixel offsets (two jp halves)
    uint32_t pixoff[2];
    {
        int khalf = (lane >> 3) & 1;
        #pragma unroll
        for (int jp = 0; jp < 2; ++jp) {
            int px = warp_n*32 + (lane & 7) + ((lane >> 4) & 1)*8 + jp*16;
            int dt = px >> 6, col = px & 63;
            pixoff[jp] = (uint32_t)(dt*66 + col)*32 + khalf*16;
        }
    }

    float acc[4][4][4];
    #pragma unroll
    for (int mt = 0; mt < 4; ++mt)
        #pragma unroll
        for (int nt = 0; nt < 4; ++nt)
            #pragma unroll
            for (int q = 0; q < 4; ++q) acc[mt][nt][q] = 0.f;

    // stage X for chunk ck into buffer ck&1 (264 rows x 32B)
    #define STAGE_X(ck) do {                                                 \
        int ciN = (ck) << 4;                                                 \
        uint32_t xd = sbX + ((ck) & 1) * XBUF;                               \
        for (int i = tid; i < 528; i += 256) {                               \
            int row = i >> 1, seg = i & 1;                                   \
            int pr  = row / 66, pc = row - pr*66;                            \
            size_t so = ((size_t)n*XP + (size_t)(h0 + pr)*66 + pc)*CIN + ciN + seg*8; \
            cp16(xd + row*32 + seg*16, g_xh + so);                           \
        }                                                                    \
    } while (0)
    // stage A for (ck, tap) into buffer s&1
    #define STAGE_A(s, ck, tap) do {                                         \
        size_t ao = ((size_t)((tap)*COUT + co0 + arow))*CIN + ((ck) << 4) + aseg*8; \
        cp16(sbA + ((s) & 1)*ABUF + arow*32 + aseg*16, g_wh + ao);           \
    } while (0)

    // prologue: X chunk 0 + A stage 0
    STAGE_X(0);
    STAGE_A(0, 0, 0);
    CP_COMMIT();

    for (int ck = 0; ck < 32; ++ck) {
        #pragma unroll 1
        for (int tap = 0; tap < 9; ++tap) {
            const int s = ck*9 + tap;
            // prefetch next stage
            if (s + 1 < 288) {
                int tapN = (tap == 8) ? 0 : tap + 1;
                int ckN  = (tap == 8) ? ck + 1 : ck;
                STAGE_A(s + 1, ckN, tapN);
            }
            if (tap == 0 && ck + 1 < 32) STAGE_X(ck + 1);
            CP_COMMIT();
            if (s + 1 < 288) CP_WAIT1(); else CP_WAIT0();
            __syncthreads();

            // ---- fragments ----
            const uint32_t ab = sbA + (s & 1)*ABUF;
            uint32_t a[4][4];
            #pragma unroll
            for (int mt = 0; mt < 4; ++mt)
                ldm_x4(a[mt], ab + (a_row + mt*16)*32 + a_col);

            const int kh = tap / 3;
            const int kw = tap - kh*3;
            const uint32_t xb = sbX + (ck & 1)*XBUF + (uint32_t)(kh*66 + kw)*32;
            uint32_t bh[2][4];
            #pragma unroll
            for (int jp = 0; jp < 2; ++jp)
                ldm_x4(bh[jp], xb + pixoff[jp]);

            // ---- mma ----
            #pragma unroll
            for (int mt = 0; mt < 4; ++mt)
                #pragma unroll
                for (int nt = 0; nt < 4; ++nt)
                    mma16816(acc[mt][nt], a[mt], &bh[nt >> 1][(nt & 1)*2]);
            __syncthreads();
        }
    }

    // ---- epilogue: demod + noise + LeakyReLU ----
    const float nw = noise_w[0];
    const int g  = lane >> 2;
    const int tg = lane & 3;
    #pragma unroll
    for (int mt = 0; mt < 4; ++mt) {
        int co = co0 + warp_m*64 + mt*16 + g;
        float d0 = g_demod[(n << 9) + co];
        float d1 = g_demod[(n << 9) + co + 8];
        #pragma unroll
        for (int nt = 0; nt < 4; ++nt) {
            int px = p0 + warp_n*32 + nt*8 + tg*2;
            float nz0 = nw * noise[(size_t)n*HW + px];
            float nz1 = nw * noise[(size_t)n*HW + px + 1];
            float v0 = acc[mt][nt][0] * d0 + nz0;
            float v1 = acc[mt][nt][1] * d0 + nz1;
            float v2 = acc[mt][nt][2] * d1 + nz0;
            float v3 = acc[mt][nt][3] * d1 + nz1;
            v0 = (v0 >= 0.f) ? v0 : 0.2f*v0;
            v1 = (v1 >= 0.f) ? v1 : 0.2f*v1;
            v2 = (v2 >= 0.f) ? v2 : 0.2f*v2;
            v3 = (v3 >= 0.f) ? v3 : 0.2f*v3;
            *(float2*)(out + (((size_t)n*COUT + co    ) << 12) + px) = make_float2(v0, v1);
            *(float2*)(out + (((size_t)n*COUT + co + 8) << 12) + px) = make_float2(v2, v3);
        }
    }
}

// ---------------- launcher ----------------
extern "C" void kernel_launch(void* const* d_in, const int* in_sizes, int n_in,
                              void* d_out, int out_size)
{
    const float* x       = (const float*)d_in[0];
    const float* style   = (const float*)d_in[1];
    const float* noise   = (const float*)d_in[2];
    const float* weight  = (const float*)d_in[3];
    const float* style_w = (const float*)d_in[4];
    const float* style_b = (const float*)d_in[5];
    const float* noise_w = (const float*)d_in[6];
    float* out           = (float*)d_out;

    k_style<<<(NB*CIN + 255)/256, 256>>>(style, style_w, style_b);
    k_wprep<<<(COUT*CIN + 255)/256, 256>>>(weight);
    k_demod<<<(NB*COUT + 255)/256, 256>>>();
    k_xzero_border<<<(NB*260*64 + 255)/256, 256>>>();
    {
        dim3 grid(HW/32, CIN/32, NB);
        dim3 block(32, 8);
        k_xprep<<<grid, block>>>(x);
    }
    {
        dim3 grid(HW/128, COUT/128, NB);   // 32 x 4 x 16 = 2048 blocks
        k_conv_mma<<<grid, 256>>>(noise, noise_w, out);
    }
}

// round 14
// speedup vs baseline: 6.7061x; 1.0352x over previous
#include <cuda_runtime.h>
#include <cuda_fp16.h>
#include <math.h>
#include <stdint.h>

// ---------------- problem constants ----------------
#define NB   16
#define CIN  512
#define COUT 512
#define HH   64
#define WW   64
#define HW   (HH*WW)
#define STY  512
#define KT   9
#define XP   4356          // padded pixels per sample: 66*66

// ---------------- scratch (device globals) ----------------
__device__ float g_s[NB*CIN];
__device__ float g_wsq[COUT*CIN];
__device__ float g_demod[NB*COUT];
// modulated x, fp16, transposed+padded: [n][P=(h+1)*66+(w+1)][ci]
__device__ __half g_xh[(size_t)NB*XP*CIN];
// weights fp16, transposed: [tap][co][ci]
__device__ __half g_wh[(size_t)KT*COUT*CIN];

// ---------------- PTX helpers ----------------
__device__ __forceinline__ uint32_t smem_u32(const void* p) {
    uint32_t a;
    asm("{ .reg .u64 t; cvta.to.shared.u64 t, %1; cvt.u32.u64 %0, t; }"
        : "=r"(a) : "l"(p));
    return a;
}
__device__ __forceinline__ void cp16(uint32_t dst, const void* src) {
    asm volatile("cp.async.cg.shared.global [%0], [%1], 16;"
                 :: "r"(dst), "l"(src) : "memory");
}
#define CP_COMMIT() asm volatile("cp.async.commit_group;" ::: "memory")
#define CP_WAIT2()  asm volatile("cp.async.wait_group 2;" ::: "memory")
#define CP_WAIT0()  asm volatile("cp.async.wait_group 0;" ::: "memory")

__device__ __forceinline__ void ldm_x4(uint32_t* r, uint32_t addr) {
    asm volatile("ldmatrix.sync.aligned.m8n8.x4.shared.b16 {%0,%1,%2,%3}, [%4];"
        : "=r"(r[0]), "=r"(r[1]), "=r"(r[2]), "=r"(r[3]) : "r"(addr));
}
__device__ __forceinline__ void mma16816(float* c, const uint32_t* a, const uint32_t* b) {
    asm volatile(
        "mma.sync.aligned.m16n8k16.row.col.f32.f16.f16.f32 "
        "{%0,%1,%2,%3}, {%4,%5,%6,%7}, {%8,%9}, {%0,%1,%2,%3};"
        : "+f"(c[0]), "+f"(c[1]), "+f"(c[2]), "+f"(c[3])
        : "r"(a[0]), "r"(a[1]), "r"(a[2]), "r"(a[3]), "r"(b[0]), "r"(b[1]));
}

// ---------------- prologue kernels ----------------
__global__ void k_style(const float* __restrict__ style,
                        const float* __restrict__ style_w,
                        const float* __restrict__ style_b)
{
    int idx = blockIdx.x * blockDim.x + threadIdx.x;
    if (idx >= NB*CIN) return;
    int n = idx >> 9, ci = idx & 511;
    const float* st = style + n * STY;
    const float* sw = style_w + ci * STY;
    float acc = 0.f;
    #pragma unroll 8
    for (int k = 0; k < STY; ++k) acc += st[k] * sw[k];
    g_s[idx] = acc + style_b[ci];
}

// wsq + fp16 weight transpose to [tap][co][ci]
__global__ void k_wprep(const float* __restrict__ weight)
{
    int idx = blockIdx.x * blockDim.x + threadIdx.x;   // COUT*CIN
    if (idx >= COUT*CIN) return;
    int co = idx >> 9, ci = idx & 511;
    const float* w = weight + (size_t)idx * KT;
    float acc = 0.f;
    #pragma unroll
    for (int tap = 0; tap < KT; ++tap) {
        float v = w[tap];
        acc += v * v;
        g_wh[((size_t)tap * COUT + co) * CIN + ci] = __float2half(v);
    }
    g_wsq[idx] = acc;
}

__global__ void k_demod()
{
    int idx = blockIdx.x * blockDim.x + threadIdx.x;
    if (idx >= NB*COUT) return;
    int n = idx >> 9, co = idx & 511;
    const float* sp = g_s + n * CIN;
    const float* wq = g_wsq + co * CIN;
    float acc = 0.f;
    #pragma unroll 8
    for (int ci = 0; ci < CIN; ++ci) { float sv = sp[ci]; acc += sv * sv * wq[ci]; }
    g_demod[idx] = rsqrtf(acc + 1e-8f);
}

// zero only the 260 border pixel-rows per sample
__global__ void k_xzero_border()
{
    int idx = blockIdx.x * blockDim.x + threadIdx.x;
    if (idx >= NB*260*64) return;
    int cv = idx & 63;
    int b  = (idx >> 6) % 260;
    int n  = idx / (260*64);
    int P;
    if (b < 66)       P = b;                       // top row
    else if (b < 132) P = 65*66 + (b - 66);        // bottom row
    else if (b < 196) P = (b - 132 + 1)*66;        // left col (rows 1..64)
    else              P = (b - 196 + 1)*66 + 65;   // right col
    size_t o = (((size_t)n * XP + P) * CIN) + cv*8;
    *(uint4*)(g_xh + o) = make_uint4(0,0,0,0);
}

// modulate + fp16 + transpose to [P][ci]
__global__ void k_xprep(const float* __restrict__ x)
{
    __shared__ float s[32][33];
    int p0  = blockIdx.x * 32;
    int ci0 = blockIdx.y * 32;
    int n   = blockIdx.z;
    int tx = threadIdx.x, ty = threadIdx.y;   // 32 x 8

    #pragma unroll
    for (int k = 0; k < 4; ++k) {
        int ci = ci0 + ty + k*8;
        float v = x[((size_t)(n*CIN + ci)) * HW + p0 + tx] * g_s[n*CIN + ci];
        s[tx][ty + k*8] = v;
    }
    __syncthreads();
    #pragma unroll
    for (int k = 0; k < 4; ++k) {
        int pl = ty + k*8;
        int p  = p0 + pl;
        int h  = p >> 6, w = p & 63;
        size_t P = (size_t)(h + 1) * 66 + (w + 1);
        size_t o = ((size_t)n * XP + P) * CIN + ci0 + tx;
        g_xh[o] = __float2half(s[pl][tx]);
    }
}

// ---------------- main MMA conv ----------------
// smem: X double buffer 2x8448, A ring 4x4096.
// Pipeline: A prefetch distance 3, one commit group per stage, wait_group 2,
// ONE __syncthreads per stage (post-wait barrier separates last-reads of a
// ring slot from its next writes).
#define XBUF 8448
#define ABUF 4096
#define SM_X 0
#define SM_A (2*XBUF)                  // 16896
#define SMEM_BYTES (2*XBUF + 4*ABUF)   // 33280
#define NSTAGE 288

__global__ void __launch_bounds__(256) k_conv_mma(
    const float* __restrict__ noise,
    const float* __restrict__ noise_w,
    float* __restrict__ out)
{
    __shared__ __align__(128) char smem[SMEM_BYTES];
    const uint32_t sb = smem_u32(smem);
    const uint32_t sbX = sb + SM_X;
    const uint32_t sbA = sb + SM_A;

    const int tid = threadIdx.x;
    const int lane = tid & 31, wid = tid >> 5;
    const int warp_m = wid >> 2;          // 0..1  (64 co)
    const int warp_n = wid & 3;           // 0..3  (32 px)

    const int pb  = blockIdx.x;           // 32 pixel blocks (128 px = 2 rows)
    const int co0 = blockIdx.y << 7;
    const int n   = blockIdx.z;
    const int p0  = pb << 7;
    const int h0  = pb << 1;              // padded rows h0..h0+3 needed

    // A staging coords
    const int arow = tid >> 1;
    const int aseg = tid & 1;

    // A fragment address components
    const uint32_t a_row = warp_m*64 + (lane & 7) + ((lane >> 3) & 1) * 8;
    const uint32_t a_col = ((lane >> 4) & 1) * 16;

    // B per-lane fixed pixel offsets (two jp halves)
    uint32_t pixoff[2];
    {
        int khalf = (lane >> 3) & 1;
        #pragma unroll
        for (int jp = 0; jp < 2; ++jp) {
            int px = warp_n*32 + (lane & 7) + ((lane >> 4) & 1)*8 + jp*16;
            int dt = px >> 6, col = px & 63;
            pixoff[jp] = (uint32_t)(dt*66 + col)*32 + khalf*16;
        }
    }

    float acc[4][4][4];
    #pragma unroll
    for (int mt = 0; mt < 4; ++mt)
        #pragma unroll
        for (int nt = 0; nt < 4; ++nt)
            #pragma unroll
            for (int q = 0; q < 4; ++q) acc[mt][nt][q] = 0.f;

    // stage X for chunk ck into buffer ck&1 (264 rows x 32B)
    #define STAGE_X(ck) do {                                                 \
        int ciN = (ck) << 4;                                                 \
        uint32_t xd = sbX + ((ck) & 1) * XBUF;                               \
        for (int i = tid; i < 528; i += 256) {                               \
            int row = i >> 1, seg = i & 1;                                   \
            int pr  = row / 66, pc = row - pr*66;                            \
            size_t so = ((size_t)n*XP + (size_t)(h0 + pr)*66 + pc)*CIN + ciN + seg*8; \
            cp16(xd + row*32 + seg*16, g_xh + so);                           \
        }                                                                    \
    } while (0)
    // stage A for stage index sA (ck = sA/9, tap = sA%9) into ring slot sA&3
    #define STAGE_A(sA) do {                                                 \
        int ckA  = (sA) / 9;                                                 \
        int tapA = (sA) - ckA*9;                                             \
        size_t ao = ((size_t)(tapA*COUT + co0 + arow))*CIN + (ckA << 4) + aseg*8; \
        cp16(sbA + ((sA) & 3)*ABUF + arow*32 + aseg*16, g_wh + ao);          \
    } while (0)

    // prologue: groups {X(0), A(0)}, {A(1)}, {A(2)}
    STAGE_X(0);
    STAGE_A(0);
    CP_COMMIT();
    STAGE_A(1);
    CP_COMMIT();
    STAGE_A(2);
    CP_COMMIT();

    for (int ck = 0; ck < 32; ++ck) {
        #pragma unroll 1
        for (int tap = 0; tap < 9; ++tap) {
            const int s = ck*9 + tap;
            if (s + 3 < NSTAGE) CP_WAIT2(); else CP_WAIT0();
            __syncthreads();

            // prefetch: A for stage s+3, X for chunk ck+1 at tap==0
            if (s + 3 < NSTAGE) STAGE_A(s + 3);
            if (tap == 0 && ck + 1 < 32) STAGE_X(ck + 1);
            CP_COMMIT();

            // ---- fragments ----
            const uint32_t ab = sbA + (s & 3)*ABUF;
            uint32_t a[4][4];
            #pragma unroll
            for (int mt = 0; mt < 4; ++mt)
                ldm_x4(a[mt], ab + (a_row + mt*16)*32 + a_col);

            const int kh = tap / 3;
            const int kw = tap - kh*3;
            const uint32_t xb = sbX + (ck & 1)*XBUF + (uint32_t)(kh*66 + kw)*32;
            uint32_t bh[2][4];
            #pragma unroll
            for (int jp = 0; jp < 2; ++jp)
                ldm_x4(bh[jp], xb + pixoff[jp]);

            // ---- mma ----
            #pragma unroll
            for (int mt = 0; mt < 4; ++mt)
                #pragma unroll
                for (int nt = 0; nt < 4; ++nt)
                    mma16816(acc[mt][nt], a[mt], &bh[nt >> 1][(nt & 1)*2]);
        }
    }

    // ---- epilogue: demod + noise + LeakyReLU ----
    const float nw = noise_w[0];
    const int g  = lane >> 2;
    const int tg = lane & 3;
    #pragma unroll
    for (int mt = 0; mt < 4; ++mt) {
        int co = co0 + warp_m*64 + mt*16 + g;
        float d0 = g_demod[(n << 9) + co];
        float d1 = g_demod[(n << 9) + co + 8];
        #pragma unroll
        for (int nt = 0; nt < 4; ++nt) {
            int px = p0 + warp_n*32 + nt*8 + tg*2;
            float nz0 = nw * noise[(size_t)n*HW + px];
            float nz1 = nw * noise[(size_t)n*HW + px + 1];
            float v0 = acc[mt][nt][0] * d0 + nz0;
            float v1 = acc[mt][nt][1] * d0 + nz1;
            float v2 = acc[mt][nt][2] * d1 + nz0;
            float v3 = acc[mt][nt][3] * d1 + nz1;
            v0 = (v0 >= 0.f) ? v0 : 0.2f*v0;
            v1 = (v1 >= 0.f) ? v1 : 0.2f*v1;
            v2 = (v2 >= 0.f) ? v2 : 0.2f*v2;
            v3 = (v3 >= 0.f) ? v3 : 0.2f*v3;
            *(float2*)(out + (((size_t)n*COUT + co    ) << 12) + px) = make_float2(v0, v1);
            *(float2*)(out + (((size_t)n*COUT + co + 8) << 12) + px) = make_float2(v2, v3);
        }
    }
}

// ---------------- launcher ----------------
extern "C" void kernel_launch(void* const* d_in, const int* in_sizes, int n_in,
                              void* d_out, int out_size)
{
    const float* x       = (const float*)d_in[0];
    const float* style   = (const float*)d_in[1];
    const float* noise   = (const float*)d_in[2];
    const float* weight  = (const float*)d_in[3];
    const float* style_w = (const float*)d_in[4];
    const float* style_b = (const float*)d_in[5];
    const float* noise_w = (const float*)d_in[6];
    float* out           = (float*)d_out;

    k_style<<<(NB*CIN + 255)/256, 256>>>(style, style_w, style_b);
    k_wprep<<<(COUT*CIN + 255)/256, 256>>>(weight);
    k_demod<<<(NB*COUT + 255)/256, 256>>>();
    k_xzero_border<<<(NB*260*64 + 255)/256, 256>>>();
    {
        dim3 grid(HW/32, CIN/32, NB);
        dim3 block(32, 8);
        k_xprep<<<grid, block>>>(x);
    }
    {
        dim3 grid(HW/128, COUT/128, NB);   // 32 x 4 x 16 = 2048 blocks
        k_conv_mma<<<grid, 256>>>(noise, noise_w, out);
    }
}